// round 2
// baseline (speedup 1.0000x reference)
#include <cuda_runtime.h>

// ---------------------------------------------------------------------------
// OuterProductMean (AlphaFold): S=256 seq, N=256 res, c_m=256, c_h=32, c_z=128
//
//  K1: per (s,n) row: LayerNorm(m) -> a = (ln@w1+b1)*mask, b = (ln@w2+b2)*mask
//      stored as g_A[row*32+c], g_B[row*32+c]  (== A[s][i*32+c] K-major layout)
//  K0: g_rnorm[i*256+j] = 1/(sum_s mask[s,i]*mask[s,j] + 1e-3)
//  K2: g_C[m][n] = sum_s g_A[s][m]*g_B[s][n]        (8192x8192x256 SGEMM, f32x2)
//  K3: out[(i,j)][z] = (sum_p C[i*32+p/32][j*32+p%32]*w_out[p][z] + b_out[z])*rnorm
// ---------------------------------------------------------------------------

#define S_DIM 256
#define N_DIM 256
#define CM    256
#define CH    32
#define CZ    128
#define NH    (N_DIM * CH)   // 8192

__device__ __align__(16) float g_A[S_DIM * NH];                 // 8.4 MB
__device__ __align__(16) float g_B[S_DIM * NH];                 // 8.4 MB
__device__ __align__(16) float g_C[(size_t)NH * NH];            // 268 MB
__device__ __align__(16) float g_rnorm[N_DIM * N_DIM];

// ---- packed f32x2 helpers (Blackwell sm_100a) ------------------------------
typedef unsigned long long ull;

__device__ __forceinline__ ull f2pack(float x, float y) {
    ull r;
    asm("mov.b64 %0, {%1, %2};" : "=l"(r) : "f"(x), "f"(y));
    return r;
}
__device__ __forceinline__ ull ffma2(ull a, ull b, ull c) {
    ull d;
    asm("fma.rn.f32x2 %0, %1, %2, %3;" : "=l"(d) : "l"(a), "l"(b), "l"(c));
    return d;
}
__device__ __forceinline__ float2 f2unpack(ull v) {
    float2 r;
    asm("mov.b64 {%0, %1}, %2;" : "=f"(r.x), "=f"(r.y) : "l"(v));
    return r;
}

// ---------------------------------------------------------------------------
// K0: reciprocal mask-norm.  block = i (256), thread = j (256)
// ---------------------------------------------------------------------------
__global__ __launch_bounds__(256) void k_norm(const float* __restrict__ mask) {
    const int i = blockIdx.x;
    const int j = threadIdx.x;
    __shared__ float colI[S_DIM];
    colI[j] = mask[j * N_DIM + i];   // mask[s=j][i]
    __syncthreads();
    float acc = 0.0f;
#pragma unroll 8
    for (int s = 0; s < S_DIM; s++) acc += colI[s] * mask[s * N_DIM + j];
    g_rnorm[i * N_DIM + j] = 1.0f / (acc + 1e-3f);
}

// ---------------------------------------------------------------------------
// K1: fused LayerNorm + dual projection. 256 threads, 32 rows per block.
// Thread tid owns output column c = tid&63 (c<32 -> a via w1, else b via w2),
// K-quarter g = tid>>6, and keeps its 64 W values in registers.
// ---------------------------------------------------------------------------
__global__ __launch_bounds__(256) void k_lnproj(
    const float* __restrict__ m, const float* __restrict__ mask,
    const float* __restrict__ lnw, const float* __restrict__ lnb,
    const float* __restrict__ w1, const float* __restrict__ b1,
    const float* __restrict__ w2, const float* __restrict__ b2)
{
    const int tid  = threadIdx.x;
    const int c    = tid & 63;
    const int g    = tid >> 6;          // 0..3: K-range [g*64, g*64+64)
    const int lane = tid & 31;
    const int wid  = tid >> 5;

    float wreg[64];
#pragma unroll
    for (int kk = 0; kk < 64; kk++) {
        const int k = g * 64 + kk;
        wreg[kk] = (c < CH) ? w1[k * CH + c] : w2[k * CH + (c - CH)];
    }
    const float bias = (c < CH) ? b1[c] : b2[c - CH];
    const float wln = lnw[tid];
    const float bln = lnb[tid];

    __shared__ float ysm[CM];
    __shared__ float red1[8], red2[8];
    __shared__ float psum[4][64];

    const int row0 = blockIdx.x * 32;
    for (int r = 0; r < 32; r++) {
        const int row = row0 + r;
        const float x = m[(size_t)row * CM + tid];

        float s1 = x, s2 = x * x;
#pragma unroll
        for (int off = 16; off; off >>= 1) {
            s1 += __shfl_xor_sync(0xffffffffu, s1, off);
            s2 += __shfl_xor_sync(0xffffffffu, s2, off);
        }
        if (lane == 0) { red1[wid] = s1; red2[wid] = s2; }
        __syncthreads();                                        // sync1

        float t1 = 0.f, t2 = 0.f;
#pragma unroll
        for (int w = 0; w < 8; w++) { t1 += red1[w]; t2 += red2[w]; }
        const float mean = t1 * (1.0f / CM);
        const float var  = t2 * (1.0f / CM) - mean * mean;
        const float inv  = rsqrtf(var + 1e-5f);
        ysm[tid] = (x - mean) * inv * wln + bln;
        __syncthreads();                                        // sync2

        float p = 0.f;
#pragma unroll
        for (int kk = 0; kk < 64; kk++) p += ysm[g * 64 + kk] * wreg[kk];
        psum[g][c] = p;
        __syncthreads();                                        // sync3

        if (tid < 64) {
            const float tot = psum[0][tid] + psum[1][tid] + psum[2][tid] + psum[3][tid];
            const float v = (tot + bias) * mask[row];
            if (tid < CH) g_A[(size_t)row * CH + tid]        = v;
            else          g_B[(size_t)row * CH + (tid - CH)] = v;
        }
    }
}

// ---------------------------------------------------------------------------
// K2: C = A^T B, M=N=8192, K=256. 128x128 block tile, BK=16, 8x8 per thread,
// accumulators packed as f32x2 pairs along n. A,B are L2-resident (8.4 MB).
// ---------------------------------------------------------------------------
__global__ __launch_bounds__(256, 2) void k_gemm1() {
    __shared__ float As[16][128];
    __shared__ float Bs[16][128];
    const int tid = threadIdx.x;
    const int tx = tid & 15;      // n
    const int ty = tid >> 4;      // m
    const int m0 = blockIdx.y * 128;
    const int n0 = blockIdx.x * 128;

    ull acc[8][4];
#pragma unroll
    for (int u = 0; u < 8; u++)
#pragma unroll
        for (int p = 0; p < 4; p++) acc[u][p] = 0ULL;

    for (int k0 = 0; k0 < S_DIM; k0 += 16) {
#pragma unroll
        for (int l = 0; l < 2; l++) {
            const int idx = tid + 256 * l;          // 512 float4 per matrix tile
            const int kk = idx >> 5;
            const int c4 = (idx & 31) * 4;
            *(float4*)&As[kk][c4] = *(const float4*)(g_A + (size_t)(k0 + kk) * NH + m0 + c4);
            *(float4*)&Bs[kk][c4] = *(const float4*)(g_B + (size_t)(k0 + kk) * NH + n0 + c4);
        }
        __syncthreads();
#pragma unroll
        for (int kk = 0; kk < 16; kk++) {
            float a[8];
            *(float4*)&a[0] = *(const float4*)&As[kk][ty * 8];
            *(float4*)&a[4] = *(const float4*)&As[kk][ty * 8 + 4];
            const ulonglong2 b01 = *(const ulonglong2*)&Bs[kk][tx * 8];
            const ulonglong2 b23 = *(const ulonglong2*)&Bs[kk][tx * 8 + 4];
            const ull bp0 = b01.x, bp1 = b01.y, bp2 = b23.x, bp3 = b23.y;
#pragma unroll
            for (int u = 0; u < 8; u++) {
                const ull pa = f2pack(a[u], a[u]);
                acc[u][0] = ffma2(pa, bp0, acc[u][0]);
                acc[u][1] = ffma2(pa, bp1, acc[u][1]);
                acc[u][2] = ffma2(pa, bp2, acc[u][2]);
                acc[u][3] = ffma2(pa, bp3, acc[u][3]);
            }
        }
        __syncthreads();
    }

#pragma unroll
    for (int u = 0; u < 8; u++) {
        const float2 v0 = f2unpack(acc[u][0]);
        const float2 v1 = f2unpack(acc[u][1]);
        const float2 v2 = f2unpack(acc[u][2]);
        const float2 v3 = f2unpack(acc[u][3]);
        float* cp = g_C + (size_t)(m0 + ty * 8 + u) * NH + n0 + tx * 8;
        *(float4*)cp       = make_float4(v0.x, v0.y, v1.x, v1.y);
        *(float4*)(cp + 4) = make_float4(v2.x, v2.y, v3.x, v3.y);
    }
}

// ---------------------------------------------------------------------------
// K3: final projection + bias + mask-norm scale.
// Block handles (i, 64 consecutive j). K loop over c (32 chunks of 32 e):
// the needed C slice per chunk is ONE contiguous 2048-float segment.
// Thread computes 8 j x 4 z outputs (f32x2 pairs along z).
// ---------------------------------------------------------------------------
__global__ __launch_bounds__(256, 2) void k_gemm2(
    const float* __restrict__ wout, const float* __restrict__ bout,
    float* __restrict__ out)
{
    __shared__ float Vs[64 * 32];     // [jj][e]
    __shared__ float Ws[32 * 128];    // [e][z]
    const int tid = threadIdx.x;
    const int i  = blockIdx.x >> 2;
    const int j0 = (blockIdx.x & 3) * 64;
    const int zq = tid & 31;
    const int jq = tid >> 5;
    const int z0 = zq * 4;
    const int jj0 = jq * 8;

    ull acc[8][2];
#pragma unroll
    for (int u = 0; u < 8; u++) { acc[u][0] = 0ULL; acc[u][1] = 0ULL; }

    for (int c = 0; c < 32; c++) {
        const float* src = g_C + (size_t)(i * 32 + c) * NH + j0 * 32;  // 2048 contiguous
#pragma unroll
        for (int l = 0; l < 2; l++) {
            const int idx = (tid + 256 * l) * 4;
            *(float4*)&Vs[idx] = *(const float4*)(src + idx);
        }
        const float* wsrc = wout + (size_t)c * 32 * CZ;                 // 4096 contiguous
#pragma unroll
        for (int l = 0; l < 4; l++) {
            const int idx = (tid + 256 * l) * 4;
            *(float4*)&Ws[idx] = *(const float4*)(wsrc + idx);
        }
        __syncthreads();
#pragma unroll
        for (int e = 0; e < 32; e++) {
            const ulonglong2 wp = *(const ulonglong2*)&Ws[e * CZ + z0];
#pragma unroll
            for (int u = 0; u < 8; u++) {
                const float a = Vs[(jj0 + u) * 32 + e];   // warp-broadcast
                const ull pa = f2pack(a, a);
                acc[u][0] = ffma2(pa, wp.x, acc[u][0]);
                acc[u][1] = ffma2(pa, wp.y, acc[u][1]);
            }
        }
        __syncthreads();
    }

    const float4 bz = *(const float4*)(bout + z0);
#pragma unroll
    for (int u = 0; u < 8; u++) {
        const int r = i * N_DIM + j0 + jj0 + u;
        const float rn = g_rnorm[r];
        const float2 v0 = f2unpack(acc[u][0]);
        const float2 v1 = f2unpack(acc[u][1]);
        float4 o;
        o.x = (v0.x + bz.x) * rn;
        o.y = (v0.y + bz.y) * rn;
        o.z = (v1.x + bz.z) * rn;
        o.w = (v1.y + bz.w) * rn;
        *(float4*)(out + (size_t)r * CZ + z0) = o;
    }
}

// ---------------------------------------------------------------------------
extern "C" void kernel_launch(void* const* d_in, const int* in_sizes, int n_in,
                              void* d_out, int out_size)
{
    (void)in_sizes; (void)n_in; (void)out_size;
    const float* m    = (const float*)d_in[0];
    const float* mask = (const float*)d_in[1];
    const float* lnw  = (const float*)d_in[2];
    const float* lnb  = (const float*)d_in[3];
    const float* w1   = (const float*)d_in[4];
    const float* b1   = (const float*)d_in[5];
    const float* w2   = (const float*)d_in[6];
    const float* b2   = (const float*)d_in[7];
    const float* wout = (const float*)d_in[8];
    const float* bout = (const float*)d_in[9];
    float* out = (float*)d_out;

    k_lnproj<<<(S_DIM * N_DIM) / 32, 256>>>(m, mask, lnw, lnb, w1, b1, w2, b2);
    k_norm<<<N_DIM, 256>>>(mask);
    dim3 g2(NH / 128, NH / 128);
    k_gemm1<<<g2, 256>>>();
    k_gemm2<<<N_DIM * 4, 256>>>(wout, bout, out);
}

// round 4
// speedup vs baseline: 1.4954x; 1.4954x over previous
#include <cuda_runtime.h>
#include <cuda_bf16.h>
#include <cstdint>

// ---------------------------------------------------------------------------
// OuterProductMean: S=256, N=256, c_m=256, c_h=32, c_z=128
//   k_lnproj : LN + dual projection -> bf16 hi/lo, K-major [m=8192][s=256]
//   k_wprep  : w_out fp32 [1024][128] -> bf16 hi/lo transposed [z=128][k=1024]
//   k_norm   : g_rnorm[i,j] = 1/(sum_s mask[s,i]mask[s,j] + 1e-3)
//   k_gemm1  : HMMA split-bf16  C[8192x8192] = A B^T (K=256), C stored bf16 hi/lo
//   k_gemm2  : HMMA split-bf16  out[(i,j),z] = (C_i W + b) * rnorm
// All PTX is sm_80-compatible (mma.sync / ldmatrix / cp.async) -> compiles for
// compute_100 (no 'a' feature set needed).
// ---------------------------------------------------------------------------

#define S_DIM 256
#define N_DIM 256
#define CM    256
#define CH    32
#define CZ    128
#define NH    8192

__device__ __align__(16) __nv_bfloat16 g_Ah[(size_t)NH * S_DIM];
__device__ __align__(16) __nv_bfloat16 g_Al[(size_t)NH * S_DIM];
__device__ __align__(16) __nv_bfloat16 g_Bh[(size_t)NH * S_DIM];
__device__ __align__(16) __nv_bfloat16 g_Bl[(size_t)NH * S_DIM];
__device__ __align__(16) __nv_bfloat16 g_Ch[(size_t)NH * NH];   // 134 MB
__device__ __align__(16) __nv_bfloat16 g_Cl[(size_t)NH * NH];   // 134 MB
__device__ __align__(16) __nv_bfloat16 g_Wh[CZ * 1024];
__device__ __align__(16) __nv_bfloat16 g_Wl[CZ * 1024];
__device__ __align__(16) float g_rnorm[N_DIM * N_DIM];

// ---- sm_80-era PTX helpers -------------------------------------------------
__device__ __forceinline__ uint32_t smem_u32(const void* p) {
    uint32_t a;
    asm("{ .reg .u64 t; cvta.to.shared.u64 t, %1; cvt.u32.u64 %0, t; }" : "=r"(a) : "l"(p));
    return a;
}
__device__ __forceinline__ void cp16(uint32_t dst, const void* src) {
    asm volatile("cp.async.cg.shared.global [%0], [%1], 16;" :: "r"(dst), "l"(src));
}
#define CP_COMMIT() asm volatile("cp.async.commit_group;" ::: "memory")
#define CP_WAIT(n)  asm volatile("cp.async.wait_group %0;" :: "n"(n) : "memory")

__device__ __forceinline__ void ldm4(uint32_t* r, uint32_t addr) {
    asm volatile("ldmatrix.sync.aligned.m8n8.x4.shared.b16 {%0,%1,%2,%3}, [%4];"
                 : "=r"(r[0]), "=r"(r[1]), "=r"(r[2]), "=r"(r[3]) : "r"(addr));
}
__device__ __forceinline__ void mma_bf16(float* c, const uint32_t* a, const uint32_t* b) {
    asm volatile(
        "mma.sync.aligned.m16n8k16.row.col.f32.bf16.bf16.f32 "
        "{%0,%1,%2,%3}, {%4,%5,%6,%7}, {%8,%9}, {%0,%1,%2,%3};"
        : "+f"(c[0]), "+f"(c[1]), "+f"(c[2]), "+f"(c[3])
        : "r"(a[0]), "r"(a[1]), "r"(a[2]), "r"(a[3]), "r"(b[0]), "r"(b[1]));
}

// smem tile geometry: 128 rows x 32 bf16, row stride 80 B (conflict-free ldmatrix)
#define ROW_B   80
#define ARR_SZ  (128 * ROW_B)        // 10240 B
#define STG_SZ  (4 * ARR_SZ)         // 40960 B per stage (4 arrays)
#define OFF_0   0
#define OFF_1   ARR_SZ
#define OFF_2   (2 * ARR_SZ)
#define OFF_3   (3 * ARR_SZ)

// ---------------------------------------------------------------------------
// K0: reciprocal mask-norm
// ---------------------------------------------------------------------------
__global__ __launch_bounds__(256) void k_norm(const float* __restrict__ mask) {
    const int i = blockIdx.x;
    const int j = threadIdx.x;
    __shared__ float colI[S_DIM];
    colI[j] = mask[j * N_DIM + i];
    __syncthreads();
    float acc = 0.0f;
#pragma unroll 8
    for (int s = 0; s < S_DIM; s++) acc += colI[s] * mask[s * N_DIM + j];
    g_rnorm[i * N_DIM + j] = 1.0f / (acc + 1e-3f);
}

// ---------------------------------------------------------------------------
// W prep: transpose + hi/lo split.  grid=128 (z), 256 threads.
// ---------------------------------------------------------------------------
__global__ __launch_bounds__(256) void k_wprep(const float* __restrict__ wout) {
    const int z = blockIdx.x;
    for (int k = threadIdx.x; k < 1024; k += 256) {
        const float w = wout[(size_t)k * CZ + z];
        const __nv_bfloat16 h = __float2bfloat16(w);
        g_Wh[z * 1024 + k] = h;
        g_Wl[z * 1024 + k] = __float2bfloat16(w - __bfloat162float(h));
    }
}

// ---------------------------------------------------------------------------
// K1: LN + dual projection, emitting transposed bf16 hi/lo (K-major).
// grid = (n=256, sg=8); 256 threads; 32 rows (same n, s = sg*32..+32).
// ---------------------------------------------------------------------------
__global__ __launch_bounds__(256) void k_lnproj(
    const float* __restrict__ m, const float* __restrict__ mask,
    const float* __restrict__ lnw, const float* __restrict__ lnb,
    const float* __restrict__ w1, const float* __restrict__ b1,
    const float* __restrict__ w2, const float* __restrict__ b2)
{
    const int tid  = threadIdx.x;
    const int c    = tid & 63;
    const int g    = tid >> 6;
    const int lane = tid & 31;
    const int wid  = tid >> 5;
    const int n    = blockIdx.x;
    const int sg   = blockIdx.y;

    float wreg[64];
#pragma unroll
    for (int kk = 0; kk < 64; kk++) {
        const int k = g * 64 + kk;
        wreg[kk] = (c < CH) ? w1[k * CH + c] : w2[k * CH + (c - CH)];
    }
    const float bias = (c < CH) ? b1[c] : b2[c - CH];
    const float wln = lnw[tid];
    const float bln = lnb[tid];

    __shared__ float ysm[CM];
    __shared__ float red1[8], red2[8];
    __shared__ float psum[4][64];
    __shared__ float aout[32][33];
    __shared__ float bout_s[32][33];

    for (int r = 0; r < 32; r++) {
        const int row = (sg * 32 + r) * N_DIM + n;
        const float x = m[(size_t)row * CM + tid];

        float s1 = x, s2 = x * x;
#pragma unroll
        for (int off = 16; off; off >>= 1) {
            s1 += __shfl_xor_sync(0xffffffffu, s1, off);
            s2 += __shfl_xor_sync(0xffffffffu, s2, off);
        }
        if (lane == 0) { red1[wid] = s1; red2[wid] = s2; }
        __syncthreads();

        float t1 = 0.f, t2 = 0.f;
#pragma unroll
        for (int w = 0; w < 8; w++) { t1 += red1[w]; t2 += red2[w]; }
        const float mean = t1 * (1.0f / CM);
        const float var  = t2 * (1.0f / CM) - mean * mean;
        const float inv  = rsqrtf(var + 1e-5f);
        ysm[tid] = (x - mean) * inv * wln + bln;
        __syncthreads();

        float p = 0.f;
#pragma unroll
        for (int kk = 0; kk < 64; kk++) p += ysm[g * 64 + kk] * wreg[kk];
        psum[g][c] = p;
        __syncthreads();

        if (tid < 64) {
            const float tot = psum[0][tid] + psum[1][tid] + psum[2][tid] + psum[3][tid];
            const float v = (tot + bias) * mask[row];
            if (tid < CH) aout[r][tid]        = v;
            else          bout_s[r][tid - CH] = v;
        }
        __syncthreads();
    }

    for (int idx = tid; idx < 1024; idx += 256) {
        const int cc = idx >> 5;
        const int sl = idx & 31;
        const size_t mrow = (size_t)(n * CH + cc) * S_DIM + sg * 32 + sl;

        const float va = aout[sl][cc];
        const __nv_bfloat16 ah = __float2bfloat16(va);
        g_Ah[mrow] = ah;
        g_Al[mrow] = __float2bfloat16(va - __bfloat162float(ah));

        const float vb = bout_s[sl][cc];
        const __nv_bfloat16 bh = __float2bfloat16(vb);
        g_Bh[mrow] = bh;
        g_Bl[mrow] = __float2bfloat16(vb - __bfloat162float(bh));
    }
}

// ---------------------------------------------------------------------------
// Shared warp-tile compute: 8 warps as 4(m) x 2(n); warp tile 32(m) x 64(n).
// One 32-wide K chunk, 3 split passes: XhYh + XhYl + XlYh.
// Arrays in stage buffer: OFF_0=Xh, OFF_1=Xl, OFF_2=Yh, OFF_3=Yl.
// ---------------------------------------------------------------------------
__device__ __forceinline__ void compute_chunk(
    uint32_t sbuf, uint32_t aoff, uint32_t boff, float acc[2][8][4])
{
#pragma unroll
    for (int ks = 0; ks < 2; ks++) {
        uint32_t aH[2][4], aL[2][4], bH[4][4], bL[4][4];
#pragma unroll
        for (int t = 0; t < 2; t++) {
            const uint32_t a = sbuf + aoff + t * (16 * ROW_B) + ks * 32;
            ldm4(aH[t], a + OFF_0);
            ldm4(aL[t], a + OFF_1);
        }
#pragma unroll
        for (int p = 0; p < 4; p++) {
            const uint32_t b = sbuf + boff + p * (16 * ROW_B) + ks * 32;
            ldm4(bH[p], b + OFF_2);
            ldm4(bL[p], b + OFF_3);
        }
#pragma unroll
        for (int t = 0; t < 2; t++) {
#pragma unroll
            for (int j = 0; j < 8; j++) {
                const uint32_t* bh = &bH[j >> 1][(j & 1) * 2];
                const uint32_t* bl = &bL[j >> 1][(j & 1) * 2];
                mma_bf16(acc[t][j], aH[t], bh);
                mma_bf16(acc[t][j], aH[t], bl);
                mma_bf16(acc[t][j], aL[t], bh);
            }
        }
    }
}

// ---------------------------------------------------------------------------
// K2: C = A B^T via HMMA split-bf16. CTA tile 128x128, K=256 in 8 chunks.
// ---------------------------------------------------------------------------
__global__ __launch_bounds__(256) void k_gemm1() {
    extern __shared__ char smraw[];
    const uint32_t sm0 = smem_u32(smraw);
    const int tid  = threadIdx.x;
    const int wid  = tid >> 5;
    const int lane = tid & 31;
    const int m0 = blockIdx.y * 128;
    const int n0 = blockIdx.x * 128;
    const int wm0 = (wid & 3) * 32;
    const int wn0 = (wid >> 2) * 64;

    // ldmatrix per-lane patterns
    const int ar = (lane & 7) + ((lane >> 3) & 1) * 8;
    const int ak = (lane >> 4) * 16;
    const int br = (lane & 7) + ((lane >> 4) << 3);
    const int bk = ((lane >> 3) & 1) * 16;
    const uint32_t aoff = (uint32_t)(wm0 + ar) * ROW_B + ak;
    const uint32_t boff = (uint32_t)(wn0 + br) * ROW_B + bk;

    float acc[2][8][4];
#pragma unroll
    for (int t = 0; t < 2; t++)
#pragma unroll
        for (int j = 0; j < 8; j++)
#pragma unroll
            for (int q = 0; q < 4; q++) acc[t][j][q] = 0.f;

    // staging lambda-ish
    auto stage = [&](int kc, uint32_t sbuf) {
#pragma unroll
        for (int l = 0; l < 2; l++) {
            const int idx = tid + 256 * l;
            const int row = idx >> 2;
            const int seg = idx & 3;
            const uint32_t d = sbuf + row * ROW_B + seg * 16;
            const size_t sa = (size_t)(m0 + row) * S_DIM + kc * 32 + seg * 8;
            const size_t sb = (size_t)(n0 + row) * S_DIM + kc * 32 + seg * 8;
            cp16(d + OFF_0, g_Ah + sa);
            cp16(d + OFF_1, g_Al + sa);
            cp16(d + OFF_2, g_Bh + sb);
            cp16(d + OFF_3, g_Bl + sb);
        }
        CP_COMMIT();
    };

    stage(0, sm0);
    stage(1, sm0 + STG_SZ);

    for (int kc = 0; kc < 8; kc++) {
        if (kc < 7) { CP_WAIT(1); } else { CP_WAIT(0); }
        __syncthreads();
        const uint32_t sbuf = sm0 + (kc & 1) * STG_SZ;
        compute_chunk(sbuf, aoff, boff, acc);
        __syncthreads();
        if (kc + 2 < 8) stage(kc + 2, sbuf);
    }

    // epilogue: bf16 hi/lo split, packed u32 stores
#pragma unroll
    for (int t = 0; t < 2; t++) {
        const int mg = m0 + wm0 + t * 16 + (lane >> 2);
#pragma unroll
        for (int j = 0; j < 8; j++) {
            const int nn = n0 + wn0 + j * 8 + (lane & 3) * 2;
            const float* c = acc[t][j];
#pragma unroll
            for (int h = 0; h < 2; h++) {            // h=0: rows mg, h=1: mg+8
                const float v0 = c[h * 2 + 0], v1 = c[h * 2 + 1];
                const __nv_bfloat16 h0 = __float2bfloat16(v0);
                const __nv_bfloat16 h1 = __float2bfloat16(v1);
                __nv_bfloat162 hp; hp.x = h0; hp.y = h1;
                __nv_bfloat162 lp;
                lp.x = __float2bfloat16(v0 - __bfloat162float(h0));
                lp.y = __float2bfloat16(v1 - __bfloat162float(h1));
                const size_t o = (size_t)(mg + h * 8) * NH + nn;
                *(uint32_t*)(g_Ch + o) = *(uint32_t*)&hp;
                *(uint32_t*)(g_Cl + o) = *(uint32_t*)&lp;
            }
        }
    }
}

// ---------------------------------------------------------------------------
// K3: out_i[j,z] = (sum_k C_i[j,k] W[k,z] + b[z]) * rnorm[i,j]
// grid = (jb=2, i=256); CTA tile 128(j) x 128(z); K=1024 in 32 chunks (1 c each).
// ---------------------------------------------------------------------------
__global__ __launch_bounds__(256) void k_gemm2(
    const float* __restrict__ bout, float* __restrict__ out)
{
    extern __shared__ char smraw[];
    const uint32_t sm0 = smem_u32(smraw);
    const int tid  = threadIdx.x;
    const int wid  = tid >> 5;
    const int lane = tid & 31;
    const int i  = blockIdx.y;
    const int j0 = blockIdx.x * 128;
    const int wm0 = (wid & 3) * 32;      // j
    const int wn0 = (wid >> 2) * 64;     // z

    const int ar = (lane & 7) + ((lane >> 3) & 1) * 8;
    const int ak = (lane >> 4) * 16;
    const int br = (lane & 7) + ((lane >> 4) << 3);
    const int bk = ((lane >> 3) & 1) * 16;
    const uint32_t aoff = (uint32_t)(wm0 + ar) * ROW_B + ak;
    const uint32_t boff = (uint32_t)(wn0 + br) * ROW_B + bk;

    float acc[2][8][4];
#pragma unroll
    for (int t = 0; t < 2; t++)
#pragma unroll
        for (int j = 0; j < 8; j++)
#pragma unroll
            for (int q = 0; q < 4; q++) acc[t][j][q] = 0.f;

    auto stage = [&](int kc, uint32_t sbuf) {
#pragma unroll
        for (int l = 0; l < 2; l++) {
            const int idx = tid + 256 * l;
            const int row = idx >> 2;     // j-row (C) or z-row (W)
            const int seg = idx & 3;
            const uint32_t d = sbuf + row * ROW_B + seg * 16;
            const size_t sc = (size_t)(i * 32 + kc) * NH + (size_t)(j0 + row) * 32 + seg * 8;
            const size_t sw = (size_t)row * 1024 + kc * 32 + seg * 8;
            cp16(d + OFF_0, g_Ch + sc);
            cp16(d + OFF_1, g_Cl + sc);
            cp16(d + OFF_2, g_Wh + sw);
            cp16(d + OFF_3, g_Wl + sw);
        }
        CP_COMMIT();
    };

    stage(0, sm0);
    stage(1, sm0 + STG_SZ);

    for (int kc = 0; kc < 32; kc++) {
        if (kc < 31) { CP_WAIT(1); } else { CP_WAIT(0); }
        __syncthreads();
        const uint32_t sbuf = sm0 + (kc & 1) * STG_SZ;
        compute_chunk(sbuf, aoff, boff, acc);
        __syncthreads();
        if (kc + 2 < 32) stage(kc + 2, sbuf);
    }

    // epilogue: + bias, * rnorm, fp32 stores
#pragma unroll
    for (int t = 0; t < 2; t++) {
        const int jg = j0 + wm0 + t * 16 + (lane >> 2);
        const float rn0 = g_rnorm[i * N_DIM + jg];
        const float rn1 = g_rnorm[i * N_DIM + jg + 8];
#pragma unroll
        for (int j = 0; j < 8; j++) {
            const int z = wn0 + j * 8 + (lane & 3) * 2;
            const float2 bz = *(const float2*)(bout + z);
            const float* c = acc[t][j];
            float2 o0, o1;
            o0.x = (c[0] + bz.x) * rn0;  o0.y = (c[1] + bz.y) * rn0;
            o1.x = (c[2] + bz.x) * rn1;  o1.y = (c[3] + bz.y) * rn1;
            *(float2*)(out + (size_t)(i * N_DIM + jg) * CZ + z)     = o0;
            *(float2*)(out + (size_t)(i * N_DIM + jg + 8) * CZ + z) = o1;
        }
    }
}

// ---------------------------------------------------------------------------
extern "C" void kernel_launch(void* const* d_in, const int* in_sizes, int n_in,
                              void* d_out, int out_size)
{
    (void)in_sizes; (void)n_in; (void)out_size;
    const float* m    = (const float*)d_in[0];
    const float* mask = (const float*)d_in[1];
    const float* lnw  = (const float*)d_in[2];
    const float* lnb  = (const float*)d_in[3];
    const float* w1   = (const float*)d_in[4];
    const float* b1   = (const float*)d_in[5];
    const float* w2   = (const float*)d_in[6];
    const float* b2   = (const float*)d_in[7];
    const float* wout = (const float*)d_in[8];
    const float* bout = (const float*)d_in[9];
    float* out = (float*)d_out;

    const int smem = 2 * STG_SZ;   // 81920 B
    cudaFuncSetAttribute((const void*)k_gemm1,
                         cudaFuncAttributeMaxDynamicSharedMemorySize, smem);
    cudaFuncSetAttribute((const void*)k_gemm2,
                         cudaFuncAttributeMaxDynamicSharedMemorySize, smem);

    k_lnproj<<<dim3(N_DIM, 8), 256>>>(m, mask, lnw, lnb, w1, b1, w2, b2);
    k_wprep<<<CZ, 256>>>(wout);
    k_norm<<<N_DIM, 256>>>(mask);
    k_gemm1<<<dim3(NH / 128, NH / 128), 256, smem>>>();
    k_gemm2<<<dim3(2, N_DIM), 256, smem>>>(bout, out);
}